// round 4
// baseline (speedup 1.0000x reference)
#include <cuda_runtime.h>
#include <cuda_bf16.h>

// EmbLoss (discriminative embedding loss), B=16, H=W=640, C=4, L=8 labels.
// Inputs (metadata order): emb f32 [B,H,W,4], instance i32 [B,H,W],
// kernel f32 [B,H,W], training_mask f32 [B,H,W]. Output: 1 float scalar.

#define BB   16
#define HW_  (640*640)
#define HW4_ (HW_/4)
#define GX   64      // blocks per batch item
#define NT   256     // threads per block

// Scratch (allocation-free: __device__ globals).
// g_sum[b][l][0..3] = kernel-region emb sums, [4] = kernel-region count.
__device__ float g_sum[BB][8][5];
__device__ float g_cnti[BB][8];   // per-label pixel counts (tm-masked instance)
__device__ float g_agg[BB][8];    // per-label aggregation-term sums

__global__ void k_zero() {
    int i = threadIdx.x;
    float* p = &g_sum[0][0][0];
    for (int j = i; j < BB*8*5; j += NT) p[j] = 0.f;
    float* q = &g_cnti[0][0];
    for (int j = i; j < BB*8; j += NT) q[j] = 0.f;
    float* r = &g_agg[0][0];
    for (int j = i; j < BB*8; j += NT) r[j] = 0.f;
}

// Pass 1: per-(b,label) sums/counts. Predicated per-thread accumulators
// (no shared atomics, no dynamic register indexing), warp butterfly + one
// predicated global atomicAdd per accumulator per warp.
__global__ __launch_bounds__(NT) void k_pass1(
    const float4* __restrict__ emb, const int4* __restrict__ inst,
    const float4* __restrict__ ker, const float4* __restrict__ tmk)
{
    const int b = blockIdx.y;
    const int base = b * HW4_;

    float s[7][5];
#pragma unroll
    for (int l = 0; l < 7; l++)
#pragma unroll
        for (int c = 0; c < 5; c++) s[l][c] = 0.f;
    float ci[6] = {0.f, 0.f, 0.f, 0.f, 0.f, 0.f};

    for (int i = blockIdx.x * NT + threadIdx.x; i < HW4_; i += GX * NT) {
        int4   iv = inst[base + i];
        float4 kv = ker[base + i];
        float4 tv = tmk[base + i];
#pragma unroll
        for (int k = 0; k < 4; k++) {
            int   li = (k==0) ? iv.x : (k==1) ? iv.y : (k==2) ? iv.z : iv.w;
            float kf = (k==0) ? kv.x : (k==1) ? kv.y : (k==2) ? kv.z : kv.w;
            float tf = (k==0) ? tv.x : (k==1) ? tv.y : (k==2) ? tv.z : tv.w;
            float4 e = emb[(base + i) * 4 + k];
            int lab = (tf > 0.5f) ? (li & 7) : 0;   // inst = where(tm, instance, 0)
            int key = (kf > 0.5f) ? lab : 0;        // inst_k = where(kr, inst, 0)
#pragma unroll
            for (int l = 1; l < 8; l++)
                if (key == l) {
                    s[l-1][0] += e.x; s[l-1][1] += e.y;
                    s[l-1][2] += e.z; s[l-1][3] += e.w;
                    s[l-1][4] += 1.f;
                }
#pragma unroll
            for (int l = 2; l < 8; l++)     // only labels 2..7 feed l_agg denom
                if (lab == l) ci[l-2] += 1.f;
        }
    }

    const unsigned lane = threadIdx.x & 31u;
#pragma unroll
    for (int l = 0; l < 7; l++)
#pragma unroll
        for (int c = 0; c < 5; c++) {
            float v = s[l][c];
#pragma unroll
            for (int o = 16; o; o >>= 1) v += __shfl_xor_sync(0xffffffffu, v, o);
            if (lane == (unsigned)((l*5 + c) & 31)) atomicAdd(&g_sum[b][l+1][c], v);
        }
#pragma unroll
    for (int l = 0; l < 6; l++) {
        float v = ci[l];
#pragma unroll
        for (int o = 16; o; o >>= 1) v += __shfl_xor_sync(0xffffffffu, v, o);
        if (lane == (unsigned)l) atomicAdd(&g_cnti[b][l+2], v);
    }
}

// Pass 2: per-pixel distance-to-mean term, accumulated per label 2..7.
// mu lives in shared (8 float4 = 32 banks, conflict-free dynamic LDS.128).
__global__ __launch_bounds__(NT) void k_pass2(
    const float4* __restrict__ emb, const int4* __restrict__ inst,
    const float4* __restrict__ tmk)
{
    __shared__ float4 s_mu[8];
    const int b = blockIdx.y;
    if (threadIdx.x < 8) {
        int l = threadIdx.x;
        float4 m = make_float4(0.f, 0.f, 0.f, 0.f);
        if (l > 0) {
            float cnt = fmaxf(g_sum[b][l][4], 1.0f);
            m.x = g_sum[b][l][0] / cnt;
            m.y = g_sum[b][l][1] / cnt;
            m.z = g_sum[b][l][2] / cnt;
            m.w = g_sum[b][l][3] / cnt;
        }
        s_mu[l] = m;
    }
    __syncthreads();

    float ag[6] = {0.f, 0.f, 0.f, 0.f, 0.f, 0.f};
    const int base = b * HW4_;
    for (int i = blockIdx.x * NT + threadIdx.x; i < HW4_; i += GX * NT) {
        int4   iv = inst[base + i];
        float4 tv = tmk[base + i];
#pragma unroll
        for (int k = 0; k < 4; k++) {
            int   li = (k==0) ? iv.x : (k==1) ? iv.y : (k==2) ? iv.z : iv.w;
            float tf = (k==0) ? tv.x : (k==1) ? tv.y : (k==2) ? tv.z : tv.w;
            float4 e = emb[(base + i) * 4 + k];
            int lab = (tf > 0.5f) ? (li & 7) : 0;
            float4 m = s_mu[lab];
            float dx = e.x - m.x, dy = e.y - m.y, dz = e.z - m.z, dw = e.w - m.w;
            float sq = dx*dx + dy*dy + dz*dz + dw*dw;
            float d  = sqrtf(sq);                       // safe_norm fwd: sqrt(0)=0
            float t  = fmaxf(d - 0.5f, 0.0f);           // DELTA_V
            float term = __logf(fmaf(t, t, 1.0f));
#pragma unroll
            for (int l = 2; l < 8; l++)
                if (lab == l) ag[l-2] += term;
        }
    }

    const unsigned lane = threadIdx.x & 31u;
#pragma unroll
    for (int l = 0; l < 6; l++) {
        float v = ag[l];
#pragma unroll
        for (int o = 16; o; o >>= 1) v += __shfl_xor_sync(0xffffffffu, v, o);
        if (lane == (unsigned)l) atomicAdd(&g_agg[b][l+2], v);
    }
}

// Finalize: per-b loss (l_agg over labels 2..7, l_dis over 42 ordered pairs
// of labels 1..7, l_reg over all 8 labels), mean over B. One warp.
__global__ void k_final(float* __restrict__ out) {
    int b = threadIdx.x;
    float loss = 0.0f;
    if (b < BB) {
        float mu[8][4];
#pragma unroll
        for (int c = 0; c < 4; c++) mu[0][c] = 0.f;
#pragma unroll
        for (int l = 1; l < 8; l++) {
            float cnt = fmaxf(g_sum[b][l][4], 1.0f);
#pragma unroll
            for (int c = 0; c < 4; c++) mu[l][c] = g_sum[b][l][c] / cnt;
        }
        // l_agg = mean over labels 2..7 of agg_sum / max(cnt_i, 1)
        float la = 0.f;
#pragma unroll
        for (int l = 2; l < 8; l++)
            la += g_agg[b][l] / fmaxf(g_cnti[b][l], 1.0f);
        la *= (1.0f / 6.0f);
        // l_dis over ordered pairs i!=j, i,j in 1..7  (42 pairs)
        float ld = 0.f;
#pragma unroll
        for (int i2 = 1; i2 < 8; i2++)
#pragma unroll
            for (int j2 = 1; j2 < 8; j2++)
                if (i2 != j2) {
                    float sq = 0.f;
#pragma unroll
                    for (int c = 0; c < 4; c++) {
                        float d = mu[i2][c] - mu[j2][c];
                        sq += d * d;
                    }
                    float dd = (sq > 0.f) ? sqrtf(sq) : 0.f;
                    float t = fmaxf(3.0f - dd, 0.0f);   // 2*DELTA_D
                    ld += logf(t * t + 1.0f);
                }
        ld *= (1.0f / 42.0f);
        // l_reg = mean over all 8 labels of log(|mu|+1) * 0.001
        float lr = 0.f;
#pragma unroll
        for (int l = 0; l < 8; l++) {
            float sq = 0.f;
#pragma unroll
            for (int c = 0; c < 4; c++) sq += mu[l][c] * mu[l][c];
            float n = (sq > 0.f) ? sqrtf(sq) : 0.f;
            lr += logf(n + 1.0f);
        }
        lr *= (0.001f / 8.0f);
        loss = la + ld + lr;
    }
#pragma unroll
    for (int o = 16; o; o >>= 1) loss += __shfl_xor_sync(0xffffffffu, loss, o);
    if (b == 0) out[0] = loss * (1.0f / BB);   // LOSS_WEIGHT = 1
}

extern "C" void kernel_launch(void* const* d_in, const int* in_sizes, int n_in,
                              void* d_out, int out_size) {
    const float4* emb = (const float4*)d_in[0];
    const int4*   ins = (const int4*)  d_in[1];
    const float4* ker = (const float4*)d_in[2];
    const float4* tmk = (const float4*)d_in[3];
    (void)in_sizes; (void)n_in; (void)out_size;

    k_zero<<<1, NT>>>();
    dim3 g(GX, BB);
    k_pass1<<<g, NT>>>(emb, ins, ker, tmk);
    k_pass2<<<g, NT>>>(emb, ins, tmk);
    k_final<<<1, 32>>>((float*)d_out);
}

// round 5
// speedup vs baseline: 1.8408x; 1.8408x over previous
#include <cuda_runtime.h>
#include <cuda_bf16.h>

// EmbLoss: B=16, H=W=640, C=4, 8 labels. Output: 1 float scalar.
// Inputs: emb f32 [B,H,W,4], instance i32, kernel f32, training_mask f32.

#define BB   16
#define HW_  (640*640)
#define HW4_ (HW_/4)
#define GX   32
#define NT   256

// Scratch (__device__ globals; zero at load, re-zeroed at end of k_final).
__device__ float g_sum[BB][8][5];   // [l][0..3]=kernel-region emb sums, [4]=count
__device__ float g_cnti[BB][8];     // per-label pixel counts (tm-masked instance)
__device__ float g_agg[BB];         // pre-weighted aggregation sums (= l_agg)

// packed float2 add (Blackwell f32x2 pipe)
#define PADD2(a, b) asm volatile("add.rn.f32x2 %0, %0, %1;" : "+l"(a) : "l"(b))

// predicated packed accumulate of emb for label L (1 SETP + 2 packed FADD)
#define ACC_LABEL(L)                                                        \
  asm volatile("{.reg .pred p; setp.eq.s32 p, %2, " #L ";\n\t"              \
               "@p add.rn.f32x2 %0, %0, %3;\n\t"                            \
               "@p add.rn.f32x2 %1, %1, %4;}\n"                             \
               : "+l"(a01[(L)-1]), "+l"(a23[(L)-1])                         \
               : "r"(key), "l"(e01), "l"(e23))

// Pass 1: per-(b,label) kernel-region emb sums + counts.
__global__ __launch_bounds__(NT) void k_pass1(
    const ulonglong2* __restrict__ emb, const int4* __restrict__ inst,
    const float4* __restrict__ ker, const float4* __restrict__ tmk)
{
    const int b = blockIdx.y;
    const int base = b * HW4_;

    unsigned long long a01[7], a23[7];
#pragma unroll
    for (int l = 0; l < 7; l++) { a01[l] = 0ull; a23[l] = 0ull; }
    unsigned ck0 = 0, ck1 = 0, cl0 = 0, cl1 = 0;   // byte-packed counters

    for (int i = blockIdx.x * NT + threadIdx.x; i < HW4_; i += GX * NT) {
        int4   iv = inst[base + i];
        float4 kv = ker[base + i];
        float4 tv = tmk[base + i];
#pragma unroll
        for (int k = 0; k < 4; k++) {
            int   li = (k==0) ? iv.x : (k==1) ? iv.y : (k==2) ? iv.z : iv.w;
            float kf = (k==0) ? kv.x : (k==1) ? kv.y : (k==2) ? kv.z : kv.w;
            float tf = (k==0) ? tv.x : (k==1) ? tv.y : (k==2) ? tv.z : tv.w;
            ulonglong2 ev = emb[(base + i) * 4 + k];
            unsigned long long e01 = ev.x, e23 = ev.y;  // (x,y),(z,w) packed
            int lab = (tf > 0.5f) ? (li & 7) : 0;
            int key = (kf > 0.5f) ? lab : 0;
            ACC_LABEL(1); ACC_LABEL(2); ACC_LABEL(3); ACC_LABEL(4);
            ACC_LABEL(5); ACC_LABEL(6); ACC_LABEL(7);
            // kernel-region counts (key); byte 0 of ck0 = label0, discarded
            unsigned incK = 1u << ((key & 3) << 3);
            if (key < 4) ck0 += incK; else ck1 += incK;
            // instance counts (lab); bytes for labels 0,1 discarded
            unsigned incL = 1u << ((lab & 3) << 3);
            if (lab < 4) cl0 += incL; else cl1 += incL;
        }
    }

    // packed warp butterfly for emb sums
#pragma unroll
    for (int l = 0; l < 7; l++) {
#pragma unroll
        for (int o = 16; o; o >>= 1) {
            unsigned long long t = __shfl_xor_sync(0xffffffffu, a01[l], o);
            PADD2(a01[l], t);
            unsigned long long u = __shfl_xor_sync(0xffffffffu, a23[l], o);
            PADD2(a23[l], u);
        }
    }
    // counts: extract bytes -> floats, scalar butterflies
    float ckf[7], clf[6];
#pragma unroll
    for (int l = 1; l < 8; l++)
        ckf[l-1] = (float)((l < 4 ? (ck0 >> (l*8)) : (ck1 >> ((l-4)*8))) & 255u);
#pragma unroll
    for (int l = 2; l < 8; l++)
        clf[l-2] = (float)((l < 4 ? (cl0 >> (l*8)) : (cl1 >> ((l-4)*8))) & 255u);
#pragma unroll
    for (int j = 0; j < 7; j++) {
#pragma unroll
        for (int o = 16; o; o >>= 1) ckf[j] += __shfl_xor_sync(0xffffffffu, ckf[j], o);
    }
#pragma unroll
    for (int j = 0; j < 6; j++) {
#pragma unroll
        for (int o = 16; o; o >>= 1) clf[j] += __shfl_xor_sync(0xffffffffu, clf[j], o);
    }

    if ((threadIdx.x & 31u) == 0) {
#pragma unroll
        for (int l = 0; l < 7; l++) {
            atomicAdd(&g_sum[b][l+1][0], __uint_as_float((unsigned)(a01[l] & 0xffffffffu)));
            atomicAdd(&g_sum[b][l+1][1], __uint_as_float((unsigned)(a01[l] >> 32)));
            atomicAdd(&g_sum[b][l+1][2], __uint_as_float((unsigned)(a23[l] & 0xffffffffu)));
            atomicAdd(&g_sum[b][l+1][3], __uint_as_float((unsigned)(a23[l] >> 32)));
            atomicAdd(&g_sum[b][l+1][4], ckf[l]);
        }
#pragma unroll
        for (int l = 0; l < 6; l++) atomicAdd(&g_cnti[b][l+2], clf[l]);
    }
}

// Pass 2: per-pixel aggregation term, pre-weighted by 1/(6*max(cnt_i,1)).
__global__ __launch_bounds__(NT) void k_pass2(
    const float4* __restrict__ emb, const int4* __restrict__ inst,
    const float4* __restrict__ tmk)
{
    __shared__ float4 s_nmu[8];   // NEGATED means (saves a subtract pattern)
    __shared__ float  s_w[8];
    const int b = blockIdx.y;
    if (threadIdx.x < 8) {
        int l = threadIdx.x;
        float4 m = make_float4(0.f, 0.f, 0.f, 0.f);
        if (l > 0) {
            float r = -1.0f / fmaxf(g_sum[b][l][4], 1.0f);
            m.x = g_sum[b][l][0] * r; m.y = g_sum[b][l][1] * r;
            m.z = g_sum[b][l][2] * r; m.w = g_sum[b][l][3] * r;
        }
        s_nmu[l] = m;
        s_w[l] = (l >= 2) ? 1.0f / (6.0f * fmaxf(g_cnti[b][l], 1.0f)) : 0.0f;
    }
    __syncthreads();

    float acc = 0.0f;
    const int base = b * HW4_;
    for (int i = blockIdx.x * NT + threadIdx.x; i < HW4_; i += GX * NT) {
        int4   iv = inst[base + i];
        float4 tv = tmk[base + i];
#pragma unroll
        for (int k = 0; k < 4; k++) {
            int   li = (k==0) ? iv.x : (k==1) ? iv.y : (k==2) ? iv.z : iv.w;
            float tf = (k==0) ? tv.x : (k==1) ? tv.y : (k==2) ? tv.z : tv.w;
            float4 e = emb[(base + i) * 4 + k];
            int lab = (tf > 0.5f) ? (li & 7) : 0;
            float4 m = s_nmu[lab];           // LDS.128, distinct banks per label
            float  w = s_w[lab];
            float dx = e.x + m.x, dy = e.y + m.y, dz = e.z + m.z, dw = e.w + m.w;
            float sq = dx*dx;
            sq = fmaf(dy, dy, sq); sq = fmaf(dz, dz, sq); sq = fmaf(dw, dw, sq);
            float d;
            asm("sqrt.approx.f32 %0, %1;" : "=f"(d) : "f"(sq));
            float t = fmaxf(d - 0.5f, 0.0f);              // DELTA_V
            float term = __logf(fmaf(t, t, 1.0f));
            acc = fmaf(term, w, acc);
        }
    }
#pragma unroll
    for (int o = 16; o; o >>= 1) acc += __shfl_xor_sync(0xffffffffu, acc, o);
    if ((threadIdx.x & 31u) == 0) atomicAdd(&g_agg[b], acc);
}

// Finalize + re-zero scratch for the next call (state invariant per launch).
__global__ void k_final(float* __restrict__ out) {
    __shared__ float sl[BB];
    int t = threadIdx.x;
    if (t < BB) {
        int b = t;
        float mu[8][4];
#pragma unroll
        for (int c = 0; c < 4; c++) mu[0][c] = 0.f;
#pragma unroll
        for (int l = 1; l < 8; l++) {
            float r = 1.0f / fmaxf(g_sum[b][l][4], 1.0f);
#pragma unroll
            for (int c = 0; c < 4; c++) mu[l][c] = g_sum[b][l][c] * r;
        }
        float la = g_agg[b];                 // already weighted & averaged
        float ld = 0.f;
#pragma unroll
        for (int i2 = 1; i2 < 8; i2++)
#pragma unroll
            for (int j2 = 1; j2 < 8; j2++)
                if (i2 != j2) {
                    float sq = 0.f;
#pragma unroll
                    for (int c = 0; c < 4; c++) {
                        float d = mu[i2][c] - mu[j2][c];
                        sq = fmaf(d, d, sq);
                    }
                    float dd = (sq > 0.f) ? sqrtf(sq) : 0.f;
                    float tt = fmaxf(3.0f - dd, 0.0f);    // 2*DELTA_D
                    ld += __logf(fmaf(tt, tt, 1.0f));
                }
        ld *= (1.0f / 42.0f);
        float lr = 0.f;
#pragma unroll
        for (int l = 0; l < 8; l++) {
            float sq = 0.f;
#pragma unroll
            for (int c = 0; c < 4; c++) sq = fmaf(mu[l][c], mu[l][c], sq);
            float n = (sq > 0.f) ? sqrtf(sq) : 0.f;
            lr += __logf(n + 1.0f);
        }
        lr *= (0.001f / 8.0f);
        sl[b] = la + ld + lr;
    }
    __syncthreads();
    if (t == 0) {
        float s = 0.f;
#pragma unroll
        for (int i = 0; i < BB; i++) s += sl[i];
        out[0] = s * (1.0f / BB);            // LOSS_WEIGHT = 1
    }
    // re-zero scratch (all reads above complete; __syncthreads ordered them)
    {
        float* p = &g_sum[0][0][0];
        for (int j = t; j < BB*8*5; j += blockDim.x) p[j] = 0.f;
        float* q = &g_cnti[0][0];
        for (int j = t; j < BB*8; j += blockDim.x) q[j] = 0.f;
        if (t < BB) g_agg[t] = 0.f;
    }
}

extern "C" void kernel_launch(void* const* d_in, const int* in_sizes, int n_in,
                              void* d_out, int out_size) {
    (void)in_sizes; (void)n_in; (void)out_size;
    dim3 g(GX, BB);
    k_pass1<<<g, NT>>>((const ulonglong2*)d_in[0], (const int4*)d_in[1],
                       (const float4*)d_in[2],    (const float4*)d_in[3]);
    k_pass2<<<g, NT>>>((const float4*)d_in[0], (const int4*)d_in[1],
                       (const float4*)d_in[3]);
    k_final<<<1, 128>>>((float*)d_out);
}